// round 2
// baseline (speedup 1.0000x reference)
#include <cuda_runtime.h>
#include <cstdint>

// ---------------- problem constants ----------------
#define BATCH 64
#define NTOK  197          // tokens (196 + cls)
#define HEADS 12
#define HDIM  64
#define CDIM  768          // HEADS*HDIM
#define CK    2304         // 3*CDIM
#define MROWS (BATCH*NTOK) // 12608
#define NRD   732          // (2*14-1)^2 + 3
#define NW    50           // ceil(197/4) words of packed int8 along m
#define BHT   (BATCH*HEADS)

// ---------------- device scratch (static; cudaMalloc is banned) -------------
__device__ float              g_qkv[(size_t)MROWS * CK];       // 116.2 MB
__device__ float              g_att[(size_t)MROWS * CDIM];     //  38.7 MB
__device__ float              g_sq[BHT];
__device__ float              g_sk[BHT];
__device__ unsigned long long g_qb[BHT * NTOK];
__device__ unsigned long long g_kb[BHT * NTOK];
__device__ unsigned int       g_vT[(size_t)BHT * HDIM * NW];   //   9.8 MB

__device__ __forceinline__ int dp4a_us(unsigned int a, unsigned int b, int c) {
    int d;
    asm("dp4a.u32.s32 %0, %1, %2, %3;" : "=r"(d) : "r"(a), "r"(b), "r"(c));
    return d;
}

// ---------------- fp32 SIMT GEMM:  C[M,N] = A[M,K] @ W[N,K]^T (+bias) -------
// 128x128 tile, BK=8, 256 threads, 8x8 microtile, register prefetch.
__global__ __launch_bounds__(256) void sgemm_nt(
    const float* __restrict__ A, const float* __restrict__ W,
    const float* __restrict__ bias, float* __restrict__ C,
    int M, int N, int K)
{
    __shared__ __align__(16) float As[8][128];
    __shared__ __align__(16) float Bs[8][128];

    const int tid = threadIdx.x;
    const int bm  = blockIdx.y * 128;
    const int bn  = blockIdx.x * 128;

    const int lr = tid >> 1;          // 0..127
    const int lc = (tid & 1) << 2;    // 0 or 4
    const int arow = bm + lr;
    const bool avalid = arow < M;     // N,K are multiples of tile dims; only M is ragged
    const float* Ap = A + (size_t)arow * K + lc;
    const float* Wp = W + (size_t)(bn + lr) * K + lc;

    const int tx = (tid & 15) << 3;   // 0..120
    const int ty = (tid >> 4) << 3;   // 0..120

    float acc[8][8];
    #pragma unroll
    for (int i = 0; i < 8; i++)
        #pragma unroll
        for (int j = 0; j < 8; j++) acc[i][j] = 0.f;

    float4 a0 = avalid ? *(const float4*)Ap : make_float4(0.f,0.f,0.f,0.f);
    float4 b0 = *(const float4*)Wp;

    int k0 = 0;
    while (true) {
        As[lc+0][lr]=a0.x; As[lc+1][lr]=a0.y; As[lc+2][lr]=a0.z; As[lc+3][lr]=a0.w;
        Bs[lc+0][lr]=b0.x; Bs[lc+1][lr]=b0.y; Bs[lc+2][lr]=b0.z; Bs[lc+3][lr]=b0.w;
        __syncthreads();

        k0 += 8;
        if (k0 < K) {
            a0 = avalid ? *(const float4*)(Ap + k0) : make_float4(0.f,0.f,0.f,0.f);
            b0 = *(const float4*)(Wp + k0);
        }

        #pragma unroll
        for (int kk = 0; kk < 8; ++kk) {
            float ar[8], br[8];
            *(float4*)&ar[0] = *(const float4*)&As[kk][ty];
            *(float4*)&ar[4] = *(const float4*)&As[kk][ty+4];
            *(float4*)&br[0] = *(const float4*)&Bs[kk][tx];
            *(float4*)&br[4] = *(const float4*)&Bs[kk][tx+4];
            #pragma unroll
            for (int i = 0; i < 8; i++)
                #pragma unroll
                for (int j = 0; j < 8; j++)
                    acc[i][j] = fmaf(ar[i], br[j], acc[i][j]);
        }
        if (k0 >= K) break;
        __syncthreads();
    }

    #pragma unroll
    for (int i = 0; i < 8; i++) {
        int r = bm + ty + i;
        if (r < M) {
            float* o = C + (size_t)r * N + bn + tx;
            #pragma unroll
            for (int j = 0; j < 8; j += 4) {
                float4 v;
                v.x = acc[i][j+0]; v.y = acc[i][j+1];
                v.z = acc[i][j+2]; v.w = acc[i][j+3];
                if (bias) {
                    v.x += bias[bn+tx+j+0]; v.y += bias[bn+tx+j+1];
                    v.z += bias[bn+tx+j+2]; v.w += bias[bn+tx+j+3];
                }
                *(float4*)(o + j) = v;
            }
        }
    }
}

// ---------------- per-(b,h) |q| / |k| mean scales ----------------
__global__ __launch_bounds__(256) void scales_kernel(const float* __restrict__ qkv)
{
    __shared__ float red[256];
    const int which = blockIdx.x & 1;          // 0=q, 1=k
    const int bh    = blockIdx.x >> 1;
    const int b = bh / HEADS, h = bh % HEADS;
    const float* base = qkv + (size_t)b * NTOK * CK + which * CDIM + h * HDIM;

    float s = 0.f;
    for (int i = threadIdx.x; i < NTOK * HDIM; i += 256) {
        int n = i >> 6, dd = i & 63;
        s += fabsf(base[(size_t)n * CK + dd]);
    }
    red[threadIdx.x] = s; __syncthreads();
    for (int o = 128; o; o >>= 1) {
        if (threadIdx.x < o) red[threadIdx.x] += red[threadIdx.x + o];
        __syncthreads();
    }
    if (threadIdx.x == 0) {
        float v = red[0] / 12608.0f;
        if (which) g_sk[bh] = v; else g_sq[bh] = v;
    }
}

// ---------------- pack: sign bits for q/k, int8-quantized transposed v ------
__global__ __launch_bounds__(256) void pack_kernel(const float* __restrict__ qkv)
{
    const int bh = blockIdx.x;
    const int b = bh / HEADS, h = bh % HEADS;
    const size_t rowbase = (size_t)b * NTOK * CK + h * HDIM;
    const float* qb_ = qkv + rowbase;                 // q slice
    const float* kb_ = qkv + rowbase + CDIM;          // k slice
    const float* vb_ = qkv + rowbase + 2 * CDIM;      // v slice

    for (int n = threadIdx.x; n < NTOK; n += 256) {
        const float* qr = qb_ + (size_t)n * CK;
        const float* kr = kb_ + (size_t)n * CK;
        unsigned long long qm = 0ull, km = 0ull;
        #pragma unroll
        for (int c4 = 0; c4 < 16; c4++) {
            float4 qv = *(const float4*)(qr + c4 * 4);
            float4 kv = *(const float4*)(kr + c4 * 4);
            if (qv.x > 0.f) qm |= 1ull << (c4*4+0);
            if (qv.y > 0.f) qm |= 1ull << (c4*4+1);
            if (qv.z > 0.f) qm |= 1ull << (c4*4+2);
            if (qv.w > 0.f) qm |= 1ull << (c4*4+3);
            if (kv.x > 0.f) km |= 1ull << (c4*4+0);
            if (kv.y > 0.f) km |= 1ull << (c4*4+1);
            if (kv.z > 0.f) km |= 1ull << (c4*4+2);
            if (kv.w > 0.f) km |= 1ull << (c4*4+3);
        }
        g_qb[bh * NTOK + n] = qm;
        g_kb[bh * NTOK + n] = km;
    }

    const float SV = 2.0f / 127.0f;   // matches reference fp32 scale exactly
    for (int i = threadIdx.x; i < HDIM * NW; i += 256) {
        int dd = i / NW, w = i % NW;
        unsigned int word = 0;
        #pragma unroll
        for (int j = 0; j < 4; j++) {
            int m = 4 * w + j;
            int vi = 0;
            if (m < NTOK) {
                float v = vb_[(size_t)m * CK + dd];
                v = fminf(fmaxf(v, -2.f), 2.f);             // clip first (ref order)
                float r = rintf(v / SV);                     // division, like ref
                r = fminf(fmaxf(r, -127.f), 127.f);
                vi = (int)r;
            }
            word |= ((unsigned)vi & 0xFFu) << (8 * j);
        }
        g_vT[(size_t)bh * HDIM * NW + i] = word;
    }
}

// ---------------- fused attention: popcount QK + bias + softmax + quantize_p
// + integer PV (dp4a).  One block per (b,h); warp per query row. ----------
__global__ __launch_bounds__(256) void attn_kernel(
    const float* __restrict__ rel_table, const int* __restrict__ rel_index,
    float* __restrict__ att)
{
    __shared__ unsigned long long qb_s[NTOK], kb_s[NTOK];
    __shared__ float rel_s[NRD];
    __shared__ unsigned int v_s[HDIM * NW];
    __shared__ __align__(4) unsigned char p_bytes[8 * 224];

    const int bh = blockIdx.x;
    const int b = bh / HEADS, h = bh % HEADS;
    const int tid = threadIdx.x;

    for (int i = tid; i < NTOK; i += 256) {
        qb_s[i] = g_qb[bh * NTOK + i];
        kb_s[i] = g_kb[bh * NTOK + i];
    }
    for (int i = tid; i < NRD; i += 256) rel_s[i] = rel_table[i * HEADS + h];
    for (int i = tid; i < HDIM * NW; i += 256) v_s[i] = g_vT[(size_t)bh * HDIM * NW + i];
    __syncthreads();

    const float sqk = g_sq[bh] * g_sk[bh];
    const float SP  = 1.0f / 255.0f;
    const float OSC = (1.0f / 255.0f) * (2.0f / 127.0f);
    const int warp = tid >> 5, lane = tid & 31;

    for (int n = warp; n < NTOK; n += 8) {
        const unsigned long long qm = qb_s[n];
        const int* ridx = rel_index + n * NTOK;

        float logit[7];
        float mx = -3.0e38f;
        #pragma unroll
        for (int t = 0; t < 7; t++) {
            int m = lane + (t << 5);
            float lg = -3.0e38f;
            if (m < NTOK) {
                int dot = 64 - 2 * __popcll(qm ^ kb_s[m]);
                lg = (sqk * (float)dot) * 0.125f + rel_s[ridx[m]];
            }
            logit[t] = lg;
            mx = fmaxf(mx, lg);
        }
        #pragma unroll
        for (int o = 16; o; o >>= 1) mx = fmaxf(mx, __shfl_xor_sync(0xffffffffu, mx, o));

        float e[7], sum = 0.f;
        #pragma unroll
        for (int t = 0; t < 7; t++) {
            int m = lane + (t << 5);
            e[t] = (m < NTOK) ? expf(logit[t] - mx) : 0.f;
            sum += e[t];
        }
        #pragma unroll
        for (int o = 16; o; o >>= 1) sum += __shfl_xor_sync(0xffffffffu, sum, o);

        unsigned char* pb = p_bytes + warp * 224;
        #pragma unroll
        for (int t = 0; t < 7; t++) {
            int m = lane + (t << 5);
            int pi = 0;
            if (m < NTOK) {
                float p = e[t] / sum;          // softmax value (ref op order)
                float r = rintf(p / SP);       // round-half-even, like jnp.round
                r = fminf(fmaxf(r, 0.f), 255.f);
                pi = (int)r;
            }
            pb[m] = (unsigned char)pi;
        }
        __syncwarp();

        const unsigned int* pw = (const unsigned int*)pb;
        const unsigned int* v0 = &v_s[lane * NW];
        const unsigned int* v1 = &v_s[(lane + 32) * NW];
        int acc0 = 0, acc1 = 0;
        #pragma unroll
        for (int w = 0; w < NW; w++) {
            unsigned int pword = pw[w];
            acc0 = dp4a_us(pword, v0[w], acc0);
            acc1 = dp4a_us(pword, v1[w], acc1);
        }

        float* orow = att + (size_t)(b * NTOK + n) * CDIM + h * HDIM;
        orow[lane]      = (float)acc0 * OSC;
        orow[lane + 32] = (float)acc1 * OSC;
        __syncwarp();   // protect p_bytes before next row's writes
    }
}

// ---------------- launcher ----------------
extern "C" void kernel_launch(void* const* d_in, const int* in_sizes, int n_in,
                              void* d_out, int out_size)
{
    const float* x         = (const float*)d_in[0];
    const float* qkv_w     = (const float*)d_in[1];
    const float* proj_w    = (const float*)d_in[2];
    const float* proj_b    = (const float*)d_in[3];
    const float* rel_table = (const float*)d_in[4];
    const int*   rel_index = (const int*)d_in[5];
    float* out = (float*)d_out;

    float *qkv_ptr = nullptr, *att_ptr = nullptr;
    cudaGetSymbolAddress((void**)&qkv_ptr, g_qkv);
    cudaGetSymbolAddress((void**)&att_ptr, g_att);

    // 1) qkv = x @ qkv_w^T        [12608,768] x [2304,768]^T
    dim3 g1(CK / 128, (MROWS + 127) / 128);
    sgemm_nt<<<g1, 256>>>(x, qkv_w, nullptr, qkv_ptr, MROWS, CK, CDIM);

    // 2) per-(b,h) scales for q,k
    scales_kernel<<<BHT * 2, 256>>>(qkv_ptr);

    // 3) sign-pack q,k; int8-quantize + transpose v
    pack_kernel<<<BHT, 256>>>(qkv_ptr);

    // 4) fused binary attention
    attn_kernel<<<BHT, 256>>>(rel_table, rel_index, att_ptr);

    // 5) out = att @ proj_w^T + proj_b
    dim3 g2(CDIM / 128, (MROWS + 127) / 128);
    sgemm_nt<<<g2, 256>>>(att_ptr, proj_w, proj_b, out, MROWS, CDIM, CDIM);
}